// round 17
// baseline (speedup 1.0000x reference)
#include <cuda_runtime.h>
#include <cuda_bf16.h>
#include <cstdint>

// ============================================================================
// BitLinear: y = (int8(x) @ ternary(W)^T) * (w_scale * a_scale / 127)
// Exact int8 IMMA (mma.sync m16n8k32 s8) GEMM, M=32768 N=1024 K=1024.
// Base sm_100 target: mma.sync + LDG only.  No tcgen05/TMA.
// R17: occupancy experiment on the R16 fragment-direct GEMM.
//      Warp tile 32x32 (acc 32 regs), CTA 64x128, launch_bounds(256,3)
//      -> 24 warps/SM (was 16).  L1 bytes/mma +33% into measured slack.
//      Falsifies "mma.sync rate ceiling" vs "latency at low occupancy".
// ============================================================================

#define EPS_F 1e-8f

static constexpr int M_TOT = 32768;
static constexpr int N_TOT = 1024;
static constexpr int K_TOT = 1024;

static constexpr int BM = 64, BN = 128;
static constexpr int KTILES = 16;                    // k-tiles of 64

// -------------------- device scratch (static; no allocations) ---------------
// A in mma-fragment order: [mgrp(2048)][kt(16)][ks(2)][lane(32)] -> uint4.
// lane l, mgrp g: x = A[g*16 + l/4      ][kt*64+ks*32+(l%4)*4 ..+3]
//                 y = A[g*16 + 8 + l/4  ][same k]
//                 z = x-row, k+16;  w = y-row, k+16.
// (exactly the m16n8k32 s8 A fragment {a0,a1,a2,a3})
__device__ uint4 g_afrag[(size_t)2048 * 1024];      // 32 MB
// B in mma-fragment order: [ngrp(128)][kt(16)][ks(2)][lane(32)] -> uint2.
// lane l: x = B[ngrp*8 + l/4][kt*64+ks*32+(l%4)*4 ..+3], y = same +16 bytes.
__device__ uint2 g_bfrag[128 * 16 * 2 * 32];        // 1 MB
__device__ float g_ascale[M_TOT];
__device__ float g_partial[1024];
__device__ float g_wscale;

// -------------------- PTX helpers -------------------------------------------
__device__ __forceinline__ void mma_s8(int* c, const uint32_t* a,
                                       uint32_t b0, uint32_t b1) {
    asm volatile(
        "mma.sync.aligned.m16n8k32.row.col.s32.s8.s8.s32 "
        "{%0,%1,%2,%3}, {%4,%5,%6,%7}, {%8,%9}, {%0,%1,%2,%3};"
        : "+r"(c[0]), "+r"(c[1]), "+r"(c[2]), "+r"(c[3])
        : "r"(a[0]), "r"(a[1]), "r"(a[2]), "r"(a[3]), "r"(b0), "r"(b1));
}

__device__ __forceinline__ uint32_t pack_q(float4 v, float inv) {
    int q0 = (int)rintf(fminf(fmaxf(v.x * inv, -128.0f), 127.0f));
    int q1 = (int)rintf(fminf(fmaxf(v.y * inv, -128.0f), 127.0f));
    int q2 = (int)rintf(fminf(fmaxf(v.z * inv, -128.0f), 127.0f));
    int q3 = (int)rintf(fminf(fmaxf(v.w * inv, -128.0f), 127.0f));
    return (uint32_t)(q0 & 0xFF) | ((uint32_t)(q1 & 0xFF) << 8)
         | ((uint32_t)(q2 & 0xFF) << 16) | ((uint32_t)(q3 & 0xFF) << 24);
}

// ============================================================================
// Kernel 1: per-block |W| partial sums (deterministic tree reduce)
// ============================================================================
__global__ void __launch_bounds__(256) wabs_kernel(const float* __restrict__ w) {
    __shared__ float sm[256];
    int t = threadIdx.x;
    size_t base = (size_t)blockIdx.x * 1024;
    float s = fabsf(w[base + t]) + fabsf(w[base + t + 256])
            + fabsf(w[base + t + 512]) + fabsf(w[base + t + 768]);
    sm[t] = s;
    __syncthreads();
    for (int o = 128; o > 0; o >>= 1) {
        if (t < o) sm[t] += sm[t + o];
        __syncthreads();
    }
    if (t == 0) g_partial[blockIdx.x] = sm[0];
}

// ============================================================================
// Kernel 2: ternary weight quant -> 8-bit B fragments.
// Each block re-derives w_scale from the 1024 partials (deterministic);
// block 0 publishes it.  One u32 scatter per thread.
// ============================================================================
__global__ void __launch_bounds__(256) wquant_kernel(const float* __restrict__ w) {
    __shared__ float sm[256];
    int t = threadIdx.x;
    float s = g_partial[t] + g_partial[t + 256] + g_partial[t + 512] + g_partial[t + 768];
    sm[t] = s;
    __syncthreads();
    for (int o = 128; o > 0; o >>= 1) {
        if (t < o) sm[t] += sm[t + o];
        __syncthreads();
    }
    float ws = sm[0] / 1048576.0f + EPS_F;
    if (blockIdx.x == 0 && t == 0) g_wscale = ws;

    int idx = (blockIdx.x * 256 + t) * 4;          // element index into W[n][k]
    float4 v = *(const float4*)(w + idx);
    float inv = 1.0f / ws;
    int q0 = (int)fminf(fmaxf(rintf(v.x * inv), -1.0f), 1.0f);
    int q1 = (int)fminf(fmaxf(rintf(v.y * inv), -1.0f), 1.0f);
    int q2 = (int)fminf(fmaxf(rintf(v.z * inv), -1.0f), 1.0f);
    int q3 = (int)fminf(fmaxf(rintf(v.w * inv), -1.0f), 1.0f);
    uint32_t p = (uint32_t)(q0 & 0xFF) | ((uint32_t)(q1 & 0xFF) << 8)
               | ((uint32_t)(q2 & 0xFF) << 16) | ((uint32_t)(q3 & 0xFF) << 24);

    int r = idx >> 10;                 // n row
    int k = idx & 1023;                // k of first element
    int kt = k >> 6;
    int ks = (k >> 5) & 1;
    int j  = (k >> 4) & 1;             // 0: .x, 1: .y
    int q  = (k >> 2) & 3;
    int lane = ((r & 7) << 2) | q;
    int ngrp = r >> 3;
    uint32_t* dst = (uint32_t*)&g_bfrag[((((ngrp * 16 + kt) * 2) + ks) << 5) + lane];
    dst[j] = p;
}

// ============================================================================
// Kernel 3: per-row activation quant -> A fragments.
// 512 threads = 16 warps = 16 rows (one mgrp).  Warp w owns row mgrp*16+w:
// per-lane max reduce, quantize, scatter into smem in fragment order, then
// one coalesced 16KB block write.
// ============================================================================
__global__ void __launch_bounds__(512) xquant_kernel(const float* __restrict__ x) {
    __shared__ uint32_t stg[4096];                  // 16 KB fragment image
    int t = threadIdx.x, w = t >> 5, lane = t & 31;
    int mgrp = blockIdx.x;
    int row = mgrp * 16 + w;
    const float4* xr = (const float4*)(x + (size_t)row * 1024);

    float4 v[8];
    float m = 0.0f;
#pragma unroll
    for (int i = 0; i < 8; i++) {
        v[i] = __ldcs(xr + lane + 32 * i);
        m = fmaxf(m, fmaxf(fmaxf(fabsf(v[i].x), fabsf(v[i].y)),
                           fmaxf(fabsf(v[i].z), fabsf(v[i].w))));
    }
#pragma unroll
    for (int o = 16; o; o >>= 1) m = fmaxf(m, __shfl_xor_sync(0xFFFFFFFFu, m, o));
    float s = m + EPS_F;
    if (lane == 0) g_ascale[row] = s;

    float inv = 127.0f / s;
    // fragment coordinates for this thread (f = lane + 32*i, k = 4f):
    //   kt = 2*i + (lane>>4), ks = (lane>>3)&1, j = (lane>>2)&1, q = lane&3
    int ks = (lane >> 3) & 1;
    int regidx = 2 * ((lane >> 2) & 1) + ((w >> 3) & 1);   // 2*j + (row-half)
    int lane_f = (w & 7) * 4 + (lane & 3);
#pragma unroll
    for (int i = 0; i < 8; i++) {
        int kt = 2 * i + (lane >> 4);
        stg[((kt * 2 + ks) * 32 + lane_f) * 4 + regidx] = pack_q(v[i], inv);
    }
    __syncthreads();

    // coalesced writeout: 1024 uint4 per mgrp
    uint4* dst = g_afrag + (size_t)mgrp * 1024;
    const uint4* src = (const uint4*)stg;
    dst[t] = src[t];
    dst[t + 512] = src[t + 512];
}

// ============================================================================
// Kernel 4: int8 IMMA GEMM — SMEM-free, barrier-free, 3 CTAs/SM.
// 256 threads = 8 warps (2 m x 4 n), warp tile 32x32, CTA tile 64x128.
// Per warp-ktile: 8 LDG.64 (B) + 2x(2 LDG.128 A + 8 mma).
// ============================================================================
__global__ void __launch_bounds__(256, 3)
gemm_kernel(float* __restrict__ out) {
    int tid = threadIdx.x;
    int wid = tid >> 5, lane = tid & 31;
    int wm = wid >> 2, wn = wid & 3;           // 2 m x 4 n warp grid
    int g = lane >> 2, q = lane & 3;
    int m0 = (int)(blockIdx.x >> 3) * BM;
    int n0 = (int)(blockIdx.x & 7) * BN;

    // A fragment pointer: warp covers mgrps (m0/16 + wm*2) .. +1.
    // mgrp stride in uint4 = 16*2*32 = 1024.
    const uint4* awp = g_afrag + (size_t)((m0 >> 4) + wm * 2) * 1024 + lane;
    // B fragment pointer: warp covers ngrps (n0/8 + wn*4) .. +3.
    const uint2* bwp = g_bfrag + (size_t)((n0 >> 3) + wn * 4) * 1024 + lane;

    int acc[2][4][4];
#pragma unroll
    for (int i = 0; i < 2; i++)
#pragma unroll
        for (int j = 0; j < 4; j++)
#pragma unroll
            for (int r = 0; r < 4; r++) acc[i][j][r] = 0;

#pragma unroll 1
    for (int kt = 0; kt < KTILES; kt++) {
        // B fragments for the whole k-tile (issue long-latency loads first)
        uint2 bv[8];
#pragma unroll
        for (int nb = 0; nb < 4; nb++) {
            bv[nb * 2 + 0] = __ldg(bwp + nb * 1024 + kt * 64);
            bv[nb * 2 + 1] = __ldg(bwp + nb * 1024 + kt * 64 + 32);
        }
#pragma unroll
        for (int ks = 0; ks < 2; ks++) {
            uint4 av[2];
#pragma unroll
            for (int mb = 0; mb < 2; mb++)
                av[mb] = __ldg(awp + mb * 1024 + kt * 64 + ks * 32);
#pragma unroll
            for (int mb = 0; mb < 2; mb++)
#pragma unroll
                for (int nb = 0; nb < 4; nb++)
                    mma_s8(acc[mb][nb], (const uint32_t*)&av[mb],
                           bv[nb * 2 + ks].x, bv[nb * 2 + ks].y);
        }
    }

    // ---- epilogue: dequant rescale + float2 stores ----
    float wsc = g_wscale * (1.0f / 127.0f);
#pragma unroll
    for (int mb = 0; mb < 2; mb++) {
        int r0 = m0 + wm * 32 + mb * 16 + g;
        float sc0 = wsc * g_ascale[r0];
        float sc1 = wsc * g_ascale[r0 + 8];
        float* o0 = out + (size_t)r0 * N_TOT + n0 + wn * 32 + q * 2;
        float* o1 = o0 + (size_t)8 * N_TOT;
#pragma unroll
        for (int nb = 0; nb < 4; nb++) {
            float2 v0, v1;
            v0.x = (float)acc[mb][nb][0] * sc0;
            v0.y = (float)acc[mb][nb][1] * sc0;
            v1.x = (float)acc[mb][nb][2] * sc1;
            v1.y = (float)acc[mb][nb][3] * sc1;
            *(float2*)(o0 + nb * 8) = v0;
            *(float2*)(o1 + nb * 8) = v1;
        }
    }
}

// ============================================================================
// Host launch
// ============================================================================
extern "C" void kernel_launch(void* const* d_in, const int* in_sizes, int n_in,
                              void* d_out, int out_size) {
    (void)in_sizes; (void)n_in; (void)out_size;
    const float* x = (const float*)d_in[0];
    const float* w = (const float*)d_in[1];
    float* out = (float*)d_out;

    wabs_kernel<<<1024, 256>>>(w);
    wquant_kernel<<<1024, 256>>>(w);
    xquant_kernel<<<M_TOT / 16, 512>>>(x);
    gemm_kernel<<<(M_TOT / BM) * (N_TOT / BN), 256>>>(out);
}